// round 7
// baseline (speedup 1.0000x reference)
#include <cuda_runtime.h>
#include <cuda_bf16.h>

#define N_NODES 100000
#define N_EDGES 1600000
#define C 64

// Scratch: aggregated features agg = segment_sum(x[col]), and CSR row ptrs.
__device__ float g_agg[(size_t)N_NODES * C];
__device__ int g_row_ptr[N_NODES + 1];

static __device__ __forceinline__ unsigned long long dup_f32x2(float x) {
    unsigned long long r;
    asm("mov.b64 %0, {%1, %1};" : "=l"(r) : "f"(x));
    return r;
}
static __device__ __forceinline__ float2 unpack_f32x2(unsigned long long v) {
    float2 r;
    asm("mov.b64 {%0, %1}, %2;" : "=f"(r.x), "=f"(r.y) : "l"(v));
    return r;
}
static __device__ __forceinline__ unsigned long long pack_f32x2(float x, float y) {
    unsigned long long r;
    asm("mov.b64 %0, {%1, %2};" : "=l"(r) : "f"(x), "f"(y));
    return r;
}
#define FMA2(acc, a, b) asm("fma.rn.f32x2 %0, %1, %2, %0;" : "+l"(acc) : "l"(a), "l"(b))

// ---------------------------------------------------------------------------
// Kernel 1: CSR row pointers, 16 edges/thread, fast-skip boundary-free windows.
// ---------------------------------------------------------------------------
__global__ __launch_bounds__(256) void rowptr_fill_kernel(const int* __restrict__ row_index) {
    const int t = blockIdx.x * blockDim.x + threadIdx.x;
    const int NT = N_EDGES / 16;                 // 100000
    if (t >= NT) return;

    const int4* r4 = (const int4*)row_index;
    int4 a = __ldg(&r4[4 * t]);
    int4 b = __ldg(&r4[4 * t + 1]);
    int4 c = __ldg(&r4[4 * t + 2]);
    int4 d = __ldg(&r4[4 * t + 3]);

    int prev = (t == 0) ? -1 : __ldg(&row_index[16 * t - 1]);
    const bool tail = (t == NT - 1);

    if (d.w == prev && !tail) return;   // no boundary in this window

    int vals[16] = {a.x, a.y, a.z, a.w, b.x, b.y, b.z, b.w,
                    c.x, c.y, c.z, c.w, d.x, d.y, d.z, d.w};
    const int ebase = 16 * t;
#pragma unroll
    for (int i = 0; i < 16; i++) {
        int cur = vals[i];
        if (cur != prev) {
            for (int n = prev + 1; n <= cur; n++) g_row_ptr[n] = ebase + i;
            prev = cur;
        }
    }
    if (tail) {
        for (int n = prev + 1; n <= N_NODES; n++) g_row_ptr[n] = N_EDGES;
    }
}

// ---------------------------------------------------------------------------
// Kernel 2: segment sum of gathered x rows -> g_agg.
// 16 lanes per node (float4 per lane), 2 nodes/warp, unroll 8 for deep MLP.
// ---------------------------------------------------------------------------
__global__ __launch_bounds__(256) void agg_kernel(const int* __restrict__ column_index,
                                                  const float* __restrict__ x) {
    const int warp = (blockIdx.x * blockDim.x + threadIdx.x) >> 5;
    const int lane = threadIdx.x & 31;
    const int half = lane >> 4;
    const int hl = lane & 15;
    const int node = warp * 2 + half;
    if (node >= N_NODES) return;

    const int start = g_row_ptr[node];
    const int end = g_row_ptr[node + 1];

    float ax = 0.f, ay = 0.f, az = 0.f, aw = 0.f;

    int e = start;
    for (; e + 7 < end; e += 8) {
        int s0 = __ldg(&column_index[e]);
        int s1 = __ldg(&column_index[e + 1]);
        int s2 = __ldg(&column_index[e + 2]);
        int s3 = __ldg(&column_index[e + 3]);
        int s4 = __ldg(&column_index[e + 4]);
        int s5 = __ldg(&column_index[e + 5]);
        int s6 = __ldg(&column_index[e + 6]);
        int s7 = __ldg(&column_index[e + 7]);
        float4 v0 = __ldg((const float4*)(x + (size_t)s0 * C) + hl);
        float4 v1 = __ldg((const float4*)(x + (size_t)s1 * C) + hl);
        float4 v2 = __ldg((const float4*)(x + (size_t)s2 * C) + hl);
        float4 v3 = __ldg((const float4*)(x + (size_t)s3 * C) + hl);
        float4 v4 = __ldg((const float4*)(x + (size_t)s4 * C) + hl);
        float4 v5 = __ldg((const float4*)(x + (size_t)s5 * C) + hl);
        float4 v6 = __ldg((const float4*)(x + (size_t)s6 * C) + hl);
        float4 v7 = __ldg((const float4*)(x + (size_t)s7 * C) + hl);
        ax += ((v0.x + v1.x) + (v2.x + v3.x)) + ((v4.x + v5.x) + (v6.x + v7.x));
        ay += ((v0.y + v1.y) + (v2.y + v3.y)) + ((v4.y + v5.y) + (v6.y + v7.y));
        az += ((v0.z + v1.z) + (v2.z + v3.z)) + ((v4.z + v5.z) + (v6.z + v7.z));
        aw += ((v0.w + v1.w) + (v2.w + v3.w)) + ((v4.w + v5.w) + (v6.w + v7.w));
    }
    for (; e + 3 < end; e += 4) {
        int s0 = __ldg(&column_index[e]);
        int s1 = __ldg(&column_index[e + 1]);
        int s2 = __ldg(&column_index[e + 2]);
        int s3 = __ldg(&column_index[e + 3]);
        float4 v0 = __ldg((const float4*)(x + (size_t)s0 * C) + hl);
        float4 v1 = __ldg((const float4*)(x + (size_t)s1 * C) + hl);
        float4 v2 = __ldg((const float4*)(x + (size_t)s2 * C) + hl);
        float4 v3 = __ldg((const float4*)(x + (size_t)s3 * C) + hl);
        ax += (v0.x + v1.x) + (v2.x + v3.x);
        ay += (v0.y + v1.y) + (v2.y + v3.y);
        az += (v0.z + v1.z) + (v2.z + v3.z);
        aw += (v0.w + v1.w) + (v2.w + v3.w);
    }
    for (; e < end; e++) {
        int s0 = __ldg(&column_index[e]);
        float4 v0 = __ldg((const float4*)(x + (size_t)s0 * C) + hl);
        ax += v0.x; ay += v0.y; az += v0.z; aw += v0.w;
    }

    ((float4*)(g_agg + (size_t)node * C))[hl] = make_float4(ax, ay, az, aw);
}

// ---------------------------------------------------------------------------
// Kernel 3: out = (g_agg @ W) * deg[row] + bias   (GEMM + fused epilogue)
// 256 threads, 128-row tile. Thread = 2 rows x 16 cols (16 FFMA2 per k).
// 32 warps/SM -> load/store phases overlap other blocks' fma phases.
// ---------------------------------------------------------------------------
__global__ __launch_bounds__(256) void gemm_kernel(const float* __restrict__ w,
                                                   const float* __restrict__ bias,
                                                   const float* __restrict__ degrees,
                                                   float* __restrict__ out) {
    __shared__ float ws[64 * 64];    // 16 KB, W row-major [k][n]
    __shared__ float xs[128 * 64];   // 32 KB, XOR-swizzled agg tile

    const int tid = threadIdx.x;
    const int wid = tid >> 5;        // 0..7
    const int l = tid & 31;
    const int rg = wid & 1;          // row group: 0 -> rows 0..63, 1 -> 64..127
    const int slice = wid >> 1;      // 16-col slice 0..3
    const long row0 = (long)blockIdx.x * 128;

    // Load W (1024 float4) cooperatively.
    const float4* w4 = (const float4*)w;
    float4* ws4 = (float4*)ws;
#pragma unroll
    for (int i = 0; i < 4; i++) ws4[tid + i * 256] = w4[tid + i * 256];

    // Load agg tile: 2048 float4 coalesced, XOR-swizzled scalar stores.
#pragma unroll
    for (int i = 0; i < 8; i++) {
        int f4 = i * 256 + tid;
        int r = f4 >> 4, c4 = f4 & 15;
        long gr = row0 + r;
        float4 v = make_float4(0.f, 0.f, 0.f, 0.f);
        if (gr < N_NODES) v = ((const float4*)g_agg)[gr * 16 + c4];
        int sw = r & 31;
        float* base = xs + r * 64;
        base[(c4 * 4 + 0) ^ sw] = v.x;
        base[(c4 * 4 + 1) ^ sw] = v.y;
        base[(c4 * 4 + 2) ^ sw] = v.z;
        base[(c4 * 4 + 3) ^ sw] = v.w;
    }
    __syncthreads();

    unsigned long long acc[2][8];
#pragma unroll
    for (int m = 0; m < 2; m++)
#pragma unroll
        for (int j = 0; j < 8; j++) acc[m][j] = 0ull;

#pragma unroll 4
    for (int k = 0; k < 64; k++) {
        unsigned long long x2[2];
#pragma unroll
        for (int m = 0; m < 2; m++)
            x2[m] = dup_f32x2(xs[(rg * 64 + m * 32 + l) * 64 + (k ^ l)]);

        const ulonglong2* wr = (const ulonglong2*)(ws + k * 64 + slice * 16);
        ulonglong2 wv0 = wr[0], wv1 = wr[1], wv2 = wr[2], wv3 = wr[3];

#pragma unroll
        for (int m = 0; m < 2; m++) {
            FMA2(acc[m][0], x2[m], wv0.x);
            FMA2(acc[m][1], x2[m], wv0.y);
            FMA2(acc[m][2], x2[m], wv1.x);
            FMA2(acc[m][3], x2[m], wv1.y);
            FMA2(acc[m][4], x2[m], wv2.x);
            FMA2(acc[m][5], x2[m], wv2.y);
            FMA2(acc[m][6], x2[m], wv3.x);
            FMA2(acc[m][7], x2[m], wv3.y);
        }
    }

    // Fused epilogue: o = acc * deg[row] + bias[col], staged via smem.
    const float2* b2 = (const float2*)bias;
    unsigned long long breg[8];
#pragma unroll
    for (int j = 0; j < 8; j++) {
        float2 bv = __ldg(b2 + slice * 8 + j);
        breg[j] = pack_f32x2(bv.x, bv.y);
    }

    __syncthreads();
    float4* xs4 = (float4*)xs;
#pragma unroll
    for (int m = 0; m < 2; m++) {
        int row = rg * 64 + m * 32 + l;
        long gr = row0 + row;
        float dg = (gr < N_NODES) ? __ldg(&degrees[gr]) : 0.f;
        unsigned long long d2 = dup_f32x2(dg);
        int rsw = row & 15;
#pragma unroll
        for (int j4 = 0; j4 < 4; j4++) {
            unsigned long long o0 = breg[2 * j4];
            unsigned long long o1 = breg[2 * j4 + 1];
            FMA2(o0, acc[m][2 * j4], d2);
            FMA2(o1, acc[m][2 * j4 + 1], d2);
            float2 A = unpack_f32x2(o0);
            float2 B = unpack_f32x2(o1);
            xs4[row * 16 + ((slice * 4 + j4) ^ rsw)] = make_float4(A.x, A.y, B.x, B.y);
        }
    }
    __syncthreads();
#pragma unroll
    for (int i = 0; i < 8; i++) {
        int f4 = i * 256 + tid;
        int row = f4 >> 4, c4 = f4 & 15;
        long gr = row0 + row;
        if (gr < N_NODES)
            ((float4*)out)[gr * 16 + c4] = xs4[row * 16 + (c4 ^ (row & 15))];
    }
}

// ---------------------------------------------------------------------------
extern "C" void kernel_launch(void* const* d_in, const int* in_sizes, int n_in,
                              void* d_out, int out_size) {
    const float* x            = (const float*)d_in[0];   // [N_NODES, 64]
    const float* weight       = (const float*)d_in[1];   // [64, 64]
    const float* bias         = (const float*)d_in[2];   // [64]
    const int*   column_index = (const int*)d_in[3];     // [N_EDGES]
    const int*   row_index    = (const int*)d_in[4];     // [N_EDGES] sorted
    const float* degrees      = (const float*)d_in[5];   // [N_NODES]
    float* out = (float*)d_out;                          // [N_NODES, 64]

    // 1) CSR row pointers: 16 edges/thread interval fill with fast-skip
    const int nt = N_EDGES / 16;
    rowptr_fill_kernel<<<(nt + 255) / 256, 256>>>(row_index);

    // 2) agg = segment_sum(x[col])
    const int warps = (N_NODES + 1) / 2;
    agg_kernel<<<(warps * 32 + 255) / 256, 256>>>(column_index, x);

    // 3) out = (agg @ W) * deg + bias
    gemm_kernel<<<(N_NODES + 127) / 128, 256>>>(weight, bias, degrees, out);
}

// round 8
// speedup vs baseline: 1.0507x; 1.0507x over previous
#include <cuda_runtime.h>
#include <cuda_bf16.h>
#include <cuda_fp16.h>

#define N_NODES 100000
#define N_EDGES 1600000
#define C 64

// Scratch: fp16 copy of x, aggregated features, CSR row ptrs.
__device__ __half g_xh[(size_t)N_NODES * C];
__device__ float g_agg[(size_t)N_NODES * C];
__device__ int g_row_ptr[N_NODES + 1];

static __device__ __forceinline__ unsigned long long dup_f32x2(float x) {
    unsigned long long r;
    asm("mov.b64 %0, {%1, %1};" : "=l"(r) : "f"(x));
    return r;
}
static __device__ __forceinline__ float2 unpack_f32x2(unsigned long long v) {
    float2 r;
    asm("mov.b64 {%0, %1}, %2;" : "=f"(r.x), "=f"(r.y) : "l"(v));
    return r;
}
static __device__ __forceinline__ unsigned long long pack_f32x2(float x, float y) {
    unsigned long long r;
    asm("mov.b64 %0, {%1, %2};" : "=l"(r) : "f"(x), "f"(y));
    return r;
}
#define FMA2(acc, a, b) asm("fma.rn.f32x2 %0, %1, %2, %0;" : "+l"(acc) : "l"(a), "l"(b))

// ---------------------------------------------------------------------------
// Kernel 0: x (fp32) -> g_xh (fp16). 8 elements per thread, fully coalesced.
// ---------------------------------------------------------------------------
__global__ __launch_bounds__(256) void cvt_kernel(const float* __restrict__ x) {
    const int t = blockIdx.x * blockDim.x + threadIdx.x;
    const int NT = N_NODES * C / 8;   // 800000
    if (t >= NT) return;
    const float4* x4 = (const float4*)x;
    float4 a = __ldg(&x4[2 * t]);
    float4 b = __ldg(&x4[2 * t + 1]);
    __half2 h[4];
    h[0] = __floats2half2_rn(a.x, a.y);
    h[1] = __floats2half2_rn(a.z, a.w);
    h[2] = __floats2half2_rn(b.x, b.y);
    h[3] = __floats2half2_rn(b.z, b.w);
    ((uint4*)g_xh)[t] = *(const uint4*)h;
}

// ---------------------------------------------------------------------------
// Kernel 1: CSR row pointers, 8 edges/thread (R6-proven), fast-skip windows.
// ---------------------------------------------------------------------------
__global__ __launch_bounds__(256) void rowptr_fill_kernel(const int* __restrict__ row_index) {
    const int t = blockIdx.x * blockDim.x + threadIdx.x;
    const int NT = N_EDGES / 8;                 // 200000
    if (t >= NT) return;

    const int4* r4 = (const int4*)row_index;
    int4 a = __ldg(&r4[2 * t]);
    int4 b = __ldg(&r4[2 * t + 1]);

    int prev = (t == 0) ? -1 : __ldg(&row_index[8 * t - 1]);
    const bool tail = (t == NT - 1);

    if (b.w == prev && !tail) return;   // no boundary in this window

    int vals[8] = {a.x, a.y, a.z, a.w, b.x, b.y, b.z, b.w};
    const int ebase = 8 * t;
#pragma unroll
    for (int i = 0; i < 8; i++) {
        int cur = vals[i];
        if (cur != prev) {
            for (int n = prev + 1; n <= cur; n++) g_row_ptr[n] = ebase + i;
            prev = cur;
        }
    }
    if (tail) {
        for (int n = prev + 1; n <= N_NODES; n++) g_row_ptr[n] = N_EDGES;
    }
}

// ---------------------------------------------------------------------------
// Kernel 2: segment sum of gathered fp16 x rows -> g_agg (fp32 accumulate).
// 16 lanes per node (8 bytes = 4 halves per lane), 2 nodes/warp, no atomics.
// Gather traffic: 128 B/edge (half of fp32).
// ---------------------------------------------------------------------------
static __device__ __forceinline__ void acc_row(float& ax, float& ay, float& az, float& aw,
                                               int src, int hl) {
    uint2 u = __ldg((const uint2*)(g_xh + (size_t)src * C) + hl);
    float2 f0 = __half22float2(*(__half2*)&u.x);
    float2 f1 = __half22float2(*(__half2*)&u.y);
    ax += f0.x; ay += f0.y; az += f1.x; aw += f1.y;
}

__global__ __launch_bounds__(256) void agg_kernel(const int* __restrict__ column_index) {
    const int warp = (blockIdx.x * blockDim.x + threadIdx.x) >> 5;
    const int lane = threadIdx.x & 31;
    const int half = lane >> 4;
    const int hl = lane & 15;
    const int node = warp * 2 + half;
    if (node >= N_NODES) return;

    const int start = g_row_ptr[node];
    const int end = g_row_ptr[node + 1];

    float ax = 0.f, ay = 0.f, az = 0.f, aw = 0.f;

    int e = start;
    for (; e + 3 < end; e += 4) {
        int s0 = __ldg(&column_index[e]);
        int s1 = __ldg(&column_index[e + 1]);
        int s2 = __ldg(&column_index[e + 2]);
        int s3 = __ldg(&column_index[e + 3]);
        acc_row(ax, ay, az, aw, s0, hl);
        acc_row(ax, ay, az, aw, s1, hl);
        acc_row(ax, ay, az, aw, s2, hl);
        acc_row(ax, ay, az, aw, s3, hl);
    }
    for (; e < end; e++) {
        int s0 = __ldg(&column_index[e]);
        acc_row(ax, ay, az, aw, s0, hl);
    }

    ((float4*)(g_agg + (size_t)node * C))[hl] = make_float4(ax, ay, az, aw);
}

// ---------------------------------------------------------------------------
// Kernel 3: out = (g_agg @ W) * deg[row] + bias  (R6-proven, 128 threads)
// ---------------------------------------------------------------------------
__global__ __launch_bounds__(128) void gemm_kernel(const float* __restrict__ w,
                                                   const float* __restrict__ bias,
                                                   const float* __restrict__ degrees,
                                                   float* __restrict__ out) {
    __shared__ float ws[64 * 64];    // 16 KB, W row-major [k][n]
    __shared__ float xs[128 * 64];   // 32 KB, XOR-swizzled agg tile

    const int tid = threadIdx.x;
    const int w_id = tid >> 5;
    const int l = tid & 31;
    const long row0 = (long)blockIdx.x * 128;

    const float4* w4 = (const float4*)w;
    float4* ws4 = (float4*)ws;
#pragma unroll
    for (int i = 0; i < 8; i++) ws4[tid + i * 128] = w4[tid + i * 128];

#pragma unroll
    for (int i = 0; i < 16; i++) {
        int f4 = i * 128 + tid;
        int r = f4 >> 4, c4 = f4 & 15;
        long gr = row0 + r;
        float4 v = make_float4(0.f, 0.f, 0.f, 0.f);
        if (gr < N_NODES) v = ((const float4*)g_agg)[gr * 16 + c4];
        int sw = r & 31;
        float* base = xs + r * 64;
        base[(c4 * 4 + 0) ^ sw] = v.x;
        base[(c4 * 4 + 1) ^ sw] = v.y;
        base[(c4 * 4 + 2) ^ sw] = v.z;
        base[(c4 * 4 + 3) ^ sw] = v.w;
    }
    __syncthreads();

    unsigned long long acc[4][8];
#pragma unroll
    for (int m = 0; m < 4; m++)
#pragma unroll
        for (int j = 0; j < 8; j++) acc[m][j] = 0ull;

#pragma unroll 4
    for (int k = 0; k < 64; k++) {
        unsigned long long x2[4];
#pragma unroll
        for (int m = 0; m < 4; m++)
            x2[m] = dup_f32x2(xs[(m * 32 + l) * 64 + (k ^ l)]);

        const ulonglong2* wr = (const ulonglong2*)(ws + k * 64 + w_id * 16);
        ulonglong2 wv0 = wr[0], wv1 = wr[1], wv2 = wr[2], wv3 = wr[3];

#pragma unroll
        for (int m = 0; m < 4; m++) {
            FMA2(acc[m][0], x2[m], wv0.x);
            FMA2(acc[m][1], x2[m], wv0.y);
            FMA2(acc[m][2], x2[m], wv1.x);
            FMA2(acc[m][3], x2[m], wv1.y);
            FMA2(acc[m][4], x2[m], wv2.x);
            FMA2(acc[m][5], x2[m], wv2.y);
            FMA2(acc[m][6], x2[m], wv3.x);
            FMA2(acc[m][7], x2[m], wv3.y);
        }
    }

    // Fused epilogue: o = acc * deg[row] + bias[col], staged via smem.
    const float2* b2 = (const float2*)bias;
    unsigned long long breg[8];
#pragma unroll
    for (int j = 0; j < 8; j++) {
        float2 bv = __ldg(b2 + w_id * 8 + j);
        breg[j] = pack_f32x2(bv.x, bv.y);
    }

    __syncthreads();
    float4* xs4 = (float4*)xs;
#pragma unroll
    for (int m = 0; m < 4; m++) {
        int row = m * 32 + l;
        long gr = row0 + row;
        float dg = (gr < N_NODES) ? __ldg(&degrees[gr]) : 0.f;
        unsigned long long d2 = dup_f32x2(dg);
        int rsw = row & 15;
#pragma unroll
        for (int j4 = 0; j4 < 4; j4++) {
            unsigned long long o0 = breg[2 * j4];
            unsigned long long o1 = breg[2 * j4 + 1];
            FMA2(o0, acc[m][2 * j4], d2);
            FMA2(o1, acc[m][2 * j4 + 1], d2);
            float2 A = unpack_f32x2(o0);
            float2 B = unpack_f32x2(o1);
            xs4[row * 16 + ((w_id * 4 + j4) ^ rsw)] = make_float4(A.x, A.y, B.x, B.y);
        }
    }
    __syncthreads();
#pragma unroll
    for (int i = 0; i < 16; i++) {
        int f4 = i * 128 + tid;
        int row = f4 >> 4, c4 = f4 & 15;
        long gr = row0 + row;
        if (gr < N_NODES)
            ((float4*)out)[gr * 16 + c4] = xs4[row * 16 + (c4 ^ (row & 15))];
    }
}

// ---------------------------------------------------------------------------
extern "C" void kernel_launch(void* const* d_in, const int* in_sizes, int n_in,
                              void* d_out, int out_size) {
    const float* x            = (const float*)d_in[0];   // [N_NODES, 64]
    const float* weight       = (const float*)d_in[1];   // [64, 64]
    const float* bias         = (const float*)d_in[2];   // [64]
    const int*   column_index = (const int*)d_in[3];     // [N_EDGES]
    const int*   row_index    = (const int*)d_in[4];     // [N_EDGES] sorted
    const float* degrees      = (const float*)d_in[5];   // [N_NODES]
    float* out = (float*)d_out;                          // [N_NODES, 64]

    // 0) fp16 copy of x (halves gather bytes)
    const int ct = N_NODES * C / 8;
    cvt_kernel<<<(ct + 255) / 256, 256>>>(x);

    // 1) CSR row pointers: 8 edges/thread interval fill with fast-skip
    const int nt = N_EDGES / 8;
    rowptr_fill_kernel<<<(nt + 255) / 256, 256>>>(row_index);

    // 2) agg = segment_sum(xh[col])  (fp32 accumulation)
    const int warps = (N_NODES + 1) / 2;
    agg_kernel<<<(warps * 32 + 255) / 256, 256>>>(column_index);

    // 3) out = (agg @ W) * deg + bias
    gemm_kernel<<<(N_NODES + 127) / 128, 128>>>(weight, bias, degrees, out);
}

// round 9
// speedup vs baseline: 1.4746x; 1.4035x over previous
#include <cuda_runtime.h>
#include <cuda_bf16.h>
#include <cuda_fp16.h>
#include <cstdint>

#define N_NODES 100000
#define N_EDGES 1600000
#define C 64

// Scratch: fp16 copy of x, fp16 aggregated features, CSR row ptrs.
__device__ __half g_xh[(size_t)N_NODES * C];
__device__ __half g_aggh[(size_t)N_NODES * C];
__device__ int g_row_ptr[N_NODES + 1];

// SW128 swizzle on byte offsets (rows of 128B): XOR bits[6:4] with bits[9:7].
#define SW(o) ((o) ^ (((o) >> 3) & 0x70))

static __device__ __forceinline__ uint32_t smem_u32(const void* p) {
    uint32_t a;
    asm("{ .reg .u64 t; cvta.to.shared.u64 t, %1; cvt.u32.u64 %0, t; }" : "=r"(a) : "l"(p));
    return a;
}
static __device__ __forceinline__ void ldsm_x4(uint32_t& r0, uint32_t& r1,
                                               uint32_t& r2, uint32_t& r3, uint32_t addr) {
    asm volatile("ldmatrix.sync.aligned.m8n8.x4.shared.b16 {%0,%1,%2,%3}, [%4];"
                 : "=r"(r0), "=r"(r1), "=r"(r2), "=r"(r3) : "r"(addr));
}
static __device__ __forceinline__ void ldsm_x4_t(uint32_t& r0, uint32_t& r1,
                                                 uint32_t& r2, uint32_t& r3, uint32_t addr) {
    asm volatile("ldmatrix.sync.aligned.m8n8.x4.trans.shared.b16 {%0,%1,%2,%3}, [%4];"
                 : "=r"(r0), "=r"(r1), "=r"(r2), "=r"(r3) : "r"(addr));
}
static __device__ __forceinline__ void mma16816(float* c, const uint32_t* a,
                                                uint32_t b0, uint32_t b1) {
    asm volatile(
        "mma.sync.aligned.m16n8k16.row.col.f32.f16.f16.f32 "
        "{%0,%1,%2,%3}, {%4,%5,%6,%7}, {%8,%9}, {%0,%1,%2,%3};"
        : "+f"(c[0]), "+f"(c[1]), "+f"(c[2]), "+f"(c[3])
        : "r"(a[0]), "r"(a[1]), "r"(a[2]), "r"(a[3]), "r"(b0), "r"(b1));
}

// ---------------------------------------------------------------------------
// Kernel 0: x (fp32) -> g_xh (fp16). 8 elements per thread, fully coalesced.
// ---------------------------------------------------------------------------
__global__ __launch_bounds__(256) void cvt_kernel(const float* __restrict__ x) {
    const int t = blockIdx.x * blockDim.x + threadIdx.x;
    const int NT = N_NODES * C / 8;   // 800000
    if (t >= NT) return;
    const float4* x4 = (const float4*)x;
    float4 a = __ldg(&x4[2 * t]);
    float4 b = __ldg(&x4[2 * t + 1]);
    __half2 h[4];
    h[0] = __floats2half2_rn(a.x, a.y);
    h[1] = __floats2half2_rn(a.z, a.w);
    h[2] = __floats2half2_rn(b.x, b.y);
    h[3] = __floats2half2_rn(b.z, b.w);
    ((uint4*)g_xh)[t] = *(const uint4*)h;
}

// ---------------------------------------------------------------------------
// Kernel 1: CSR row pointers, 8 edges/thread, fast-skip boundary-free windows.
// ---------------------------------------------------------------------------
__global__ __launch_bounds__(256) void rowptr_fill_kernel(const int* __restrict__ row_index) {
    const int t = blockIdx.x * blockDim.x + threadIdx.x;
    const int NT = N_EDGES / 8;                 // 200000
    if (t >= NT) return;

    const int4* r4 = (const int4*)row_index;
    int4 a = __ldg(&r4[2 * t]);
    int4 b = __ldg(&r4[2 * t + 1]);

    int prev = (t == 0) ? -1 : __ldg(&row_index[8 * t - 1]);
    const bool tail = (t == NT - 1);

    if (b.w == prev && !tail) return;   // no boundary in this window

    int vals[8] = {a.x, a.y, a.z, a.w, b.x, b.y, b.z, b.w};
    const int ebase = 8 * t;
#pragma unroll
    for (int i = 0; i < 8; i++) {
        int cur = vals[i];
        if (cur != prev) {
            for (int n = prev + 1; n <= cur; n++) g_row_ptr[n] = ebase + i;
            prev = cur;
        }
    }
    if (tail) {
        for (int n = prev + 1; n <= N_NODES; n++) g_row_ptr[n] = N_EDGES;
    }
}

// ---------------------------------------------------------------------------
// Kernel 2: segment sum of gathered fp16 x rows, fp32 accumulate,
// fp16 store to g_aggh. 16 lanes/node (8B per lane), 2 nodes/warp.
// ---------------------------------------------------------------------------
static __device__ __forceinline__ void acc_row(float& ax, float& ay, float& az, float& aw,
                                               int src, int hl) {
    uint2 u = __ldg((const uint2*)(g_xh + (size_t)src * C) + hl);
    float2 f0 = __half22float2(*(__half2*)&u.x);
    float2 f1 = __half22float2(*(__half2*)&u.y);
    ax += f0.x; ay += f0.y; az += f1.x; aw += f1.y;
}

__global__ __launch_bounds__(256) void agg_kernel(const int* __restrict__ column_index) {
    const int warp = (blockIdx.x * blockDim.x + threadIdx.x) >> 5;
    const int lane = threadIdx.x & 31;
    const int half = lane >> 4;
    const int hl = lane & 15;
    const int node = warp * 2 + half;
    if (node >= N_NODES) return;

    const int start = g_row_ptr[node];
    const int end = g_row_ptr[node + 1];

    float ax = 0.f, ay = 0.f, az = 0.f, aw = 0.f;

    int e = start;
    for (; e + 3 < end; e += 4) {
        int s0 = __ldg(&column_index[e]);
        int s1 = __ldg(&column_index[e + 1]);
        int s2 = __ldg(&column_index[e + 2]);
        int s3 = __ldg(&column_index[e + 3]);
        acc_row(ax, ay, az, aw, s0, hl);
        acc_row(ax, ay, az, aw, s1, hl);
        acc_row(ax, ay, az, aw, s2, hl);
        acc_row(ax, ay, az, aw, s3, hl);
    }
    for (; e < end; e++) {
        int s0 = __ldg(&column_index[e]);
        acc_row(ax, ay, az, aw, s0, hl);
    }

    __half2 h0 = __floats2half2_rn(ax, ay);
    __half2 h1 = __floats2half2_rn(az, aw);
    ((uint2*)(g_aggh + (size_t)node * C))[hl] =
        make_uint2(*(uint32_t*)&h0, *(uint32_t*)&h1);
}

// ---------------------------------------------------------------------------
// Kernel 3: out = (g_aggh @ W) * deg[row] + bias  — fp16 HMMA, fp32 accumulate.
// 128 threads (4 warps), 128-row tile; warp computes 32 rows x 64 cols via
// mma.m16n8k16. SW128-swizzled smem + ldmatrix, conflict-free.
// ---------------------------------------------------------------------------
__global__ __launch_bounds__(128) void gemm_mma_kernel(const float* __restrict__ w,
                                                       const float* __restrict__ bias,
                                                       const float* __restrict__ degrees,
                                                       float* __restrict__ out) {
    __shared__ __align__(128) __half As[128 * 64];   // 16 KB
    __shared__ __align__(128) __half Ws[64 * 64];    // 8 KB

    const int tid = threadIdx.x;
    const int wid = tid >> 5;
    const int lane = tid & 31;
    const long row0 = (long)blockIdx.x * 128;

    // --- Load W (fp32 -> fp16), swizzled. 1024 float4 chunks.
    {
        const float4* w4 = (const float4*)w;
        char* wsb = (char*)Ws;
#pragma unroll
        for (int i = 0; i < 8; i++) {
            int ch = i * 128 + tid;          // 0..1023
            int k = ch >> 4, n4 = ch & 15;   // 4 floats at col n4*4
            float4 v = __ldg(&w4[ch]);
            __half2 h0 = __floats2half2_rn(v.x, v.y);
            __half2 h1 = __floats2half2_rn(v.z, v.w);
            uint2 pk = make_uint2(*(uint32_t*)&h0, *(uint32_t*)&h1);
            *(uint2*)(wsb + SW(k * 128 + n4 * 8)) = pk;
        }
    }

    // --- Load A tile (fp16 agg rows), swizzled. 1024 uint4 (16B) chunks.
    {
        const uint4* a4 = (const uint4*)g_aggh;
        char* asb = (char*)As;
#pragma unroll
        for (int i = 0; i < 8; i++) {
            int ch = i * 128 + tid;          // 0..1023
            int r = ch >> 3, cg = ch & 7;    // 8 halves at col cg*8
            long gr = row0 + r;
            uint4 v = make_uint4(0u, 0u, 0u, 0u);
            if (gr < N_NODES) v = __ldg(&a4[gr * 8 + cg]);
            *(uint4*)(asb + SW(r * 128 + cg * 16)) = v;
        }
    }
    __syncthreads();

    const uint32_t as_base = smem_u32(As);
    const uint32_t ws_base = smem_u32(Ws);
    const int wrow = wid * 32;
    const int lr = lane & 15;
    const int lc = lane >> 4;

    float c[2][8][4];
#pragma unroll
    for (int mt = 0; mt < 2; mt++)
#pragma unroll
        for (int nt = 0; nt < 8; nt++)
#pragma unroll
            for (int j = 0; j < 4; j++) c[mt][nt][j] = 0.f;

#pragma unroll
    for (int kc = 0; kc < 4; kc++) {
        // A fragments for the two 16-row tiles of this warp
        uint32_t a[2][4];
#pragma unroll
        for (int mt = 0; mt < 2; mt++) {
            uint32_t addr = as_base +
                SW((wrow + mt * 16 + lr) * 128 + kc * 32 + lc * 16);
            ldsm_x4(a[mt][0], a[mt][1], a[mt][2], a[mt][3], addr);
        }
        // B fragments: 4 x ldmatrix.x4.trans cover 8 n-tiles
#pragma unroll
        for (int np = 0; np < 4; np++) {
            uint32_t b0, b1, b2, b3;
            uint32_t addr = ws_base +
                SW((kc * 16 + lr) * 128 + (np * 16 + lc * 8) * 2);
            ldsm_x4_t(b0, b1, b2, b3, addr);
#pragma unroll
            for (int mt = 0; mt < 2; mt++) {
                mma16816(c[mt][2 * np], a[mt], b0, b1);
                mma16816(c[mt][2 * np + 1], a[mt], b2, b3);
            }
        }
    }

    // --- Epilogue: o = c * deg[row] + bias[col], direct float2 stores.
    const int qr = lane >> 2;
    const int qc = (lane & 3) * 2;
    float2 bv[8];
#pragma unroll
    for (int nt = 0; nt < 8; nt++)
        bv[nt] = __ldg((const float2*)(bias + nt * 8 + qc));

#pragma unroll
    for (int mt = 0; mt < 2; mt++) {
        long rlo = row0 + wrow + mt * 16 + qr;
        long rhi = rlo + 8;
        float dlo = (rlo < N_NODES) ? __ldg(&degrees[rlo]) : 0.f;
        float dhi = (rhi < N_NODES) ? __ldg(&degrees[rhi]) : 0.f;
#pragma unroll
        for (int nt = 0; nt < 8; nt++) {
            if (rlo < N_NODES) {
                float2 o;
                o.x = c[mt][nt][0] * dlo + bv[nt].x;
                o.y = c[mt][nt][1] * dlo + bv[nt].y;
                *(float2*)(out + (size_t)rlo * C + nt * 8 + qc) = o;
            }
            if (rhi < N_NODES) {
                float2 o;
                o.x = c[mt][nt][2] * dhi + bv[nt].x;
                o.y = c[mt][nt][3] * dhi + bv[nt].y;
                *(float2*)(out + (size_t)rhi * C + nt * 8 + qc) = o;
            }
        }
    }
}

// ---------------------------------------------------------------------------
extern "C" void kernel_launch(void* const* d_in, const int* in_sizes, int n_in,
                              void* d_out, int out_size) {
    const float* x            = (const float*)d_in[0];   // [N_NODES, 64]
    const float* weight       = (const float*)d_in[1];   // [64, 64]
    const float* bias         = (const float*)d_in[2];   // [64]
    const int*   column_index = (const int*)d_in[3];     // [N_EDGES]
    const int*   row_index    = (const int*)d_in[4];     // [N_EDGES] sorted
    const float* degrees      = (const float*)d_in[5];   // [N_NODES]
    float* out = (float*)d_out;                          // [N_NODES, 64]

    // 0) fp16 copy of x (halves gather bytes)
    const int ct = N_NODES * C / 8;
    cvt_kernel<<<(ct + 255) / 256, 256>>>(x);

    // 1) CSR row pointers: 8 edges/thread interval fill with fast-skip
    const int nt = N_EDGES / 8;
    rowptr_fill_kernel<<<(nt + 255) / 256, 256>>>(row_index);

    // 2) agg = segment_sum(xh[col]) -> fp16
    const int warps = (N_NODES + 1) / 2;
    agg_kernel<<<(warps * 32 + 255) / 256, 256>>>(column_index);

    // 3) out = (agg @ W) * deg + bias   (HMMA)
    gemm_mma_kernel<<<(N_NODES + 127) / 128, 128>>>(weight, bias, degrees, out);
}